// round 10
// baseline (speedup 1.0000x reference)
#include <cuda_runtime.h>
#include <cstdint>
#include <math.h>

#define T_  512
#define B_  32
#define H_  1024
#define BH  32768
#define OUTMAIN 16777216  // T*B*H

// ---- scratch (device globals; allocation-free rule) ----
__device__ float g_gx[(size_t)T_ * B_ * 4096];  // [T*B][4H] input-projection gates
__device__ float g_out0[(size_t)T_ * BH];       // layer-0 outputs [t][b][n]
__device__ float g_h[(size_t)(T_ + 1) * BH];    // UNIQUE per-step transposed h: [t][n][b]
__device__ float g_c[2][BH];                    // final cell state per layer [b*H + n]
__device__ unsigned g_count;                    // global barrier counter

// ---- f32x2 helpers ----
__device__ __forceinline__ unsigned long long pack2(float x) {
    unsigned u = __float_as_uint(x);
    unsigned long long r;
    asm("mov.b64 %0, {%1, %1};" : "=l"(r) : "r"(u));
    return r;
}
__device__ __forceinline__ void ffma2(unsigned long long& d, unsigned long long a,
                                      unsigned long long b) {
    asm("fma.rn.f32x2 %0, %1, %2, %0;" : "+l"(d) : "l"(a), "l"(b));
}
__device__ __forceinline__ float2 unpack2(unsigned long long v) {
    return make_float2(__uint_as_float((unsigned)v), __uint_as_float((unsigned)(v >> 32)));
}
__device__ __forceinline__ float sigm(float x) { return 1.0f / (1.0f + expf(-x)); }

// ---- formally correct gpu-scope release/acquire barrier primitives ----
__device__ __forceinline__ void bar_arrive_release() {
    asm volatile("red.release.gpu.global.add.u32 [%0], %1;"
                 :: "l"(&g_count), "r"(1u) : "memory");
}
__device__ __forceinline__ unsigned bar_peek_acquire() {
    unsigned v;
    asm volatile("ld.acquire.gpu.global.u32 %0, [%1];"
                 : "=r"(v) : "l"(&g_count) : "memory");
    return v;
}

__global__ void zero_cnt() { g_count = 0u; }

// ================= input-projection GEMM =================
// g_gx[r][c] = sum_d A[r][d]*Wih[c][d] + bih[c] + bhh[c],  r = t*B + b
// xlayout=1: A is x[B,T,I] (row r -> x[b][t]); xlayout=0: A = g_out0 row-major.
__global__ void __launch_bounds__(256) gx_gemm(const float* __restrict__ A,
                                               const float* __restrict__ Wih,
                                               const float* __restrict__ bih,
                                               const float* __restrict__ bhh,
                                               int xlayout) {
    __shared__ __align__(16) float As[32][132];
    __shared__ __align__(16) float Ws[32][68];
    const int tid = threadIdx.x;
    const int rowTile = blockIdx.y * 128, colTile = blockIdx.x * 64;
    const int kq = tid & 7;
    const int rr = tid >> 3;
    const int r0 = (tid >> 4) * 8;
    const int c0 = (tid & 15) * 4;
    const float* Asrc = xlayout ? A : g_out0;

    unsigned long long acc[4][4];
#pragma unroll
    for (int i = 0; i < 4; i++)
#pragma unroll
        for (int j = 0; j < 4; j++) acc[i][j] = 0ull;

    for (int kc = 0; kc < 1024; kc += 32) {
#pragma unroll
        for (int it = 0; it < 4; it++) {
            int r = rr + it * 32;
            int R = rowTile + r;
            size_t base = xlayout ? ((size_t)(R & 31) * 512 + (size_t)(R >> 5)) * 1024
                                  : (size_t)R * 1024;
            float4 v = *(const float4*)(Asrc + base + kc + kq * 4);
            As[kq * 4 + 0][r] = v.x; As[kq * 4 + 1][r] = v.y;
            As[kq * 4 + 2][r] = v.z; As[kq * 4 + 3][r] = v.w;
        }
#pragma unroll
        for (int it = 0; it < 2; it++) {
            int c = rr + it * 32;
            float4 v = *(const float4*)(Wih + (size_t)(colTile + c) * 1024 + kc + kq * 4);
            Ws[kq * 4 + 0][c] = v.x; Ws[kq * 4 + 1][c] = v.y;
            Ws[kq * 4 + 2][c] = v.z; Ws[kq * 4 + 3][c] = v.w;
        }
        __syncthreads();
#pragma unroll
        for (int k = 0; k < 32; k++) {
            ulonglong2 a01 = *(const ulonglong2*)&As[k][r0];
            ulonglong2 a23 = *(const ulonglong2*)&As[k][r0 + 4];
            float4 wv = *(const float4*)&Ws[k][c0];
            float wj[4] = {wv.x, wv.y, wv.z, wv.w};
#pragma unroll
            for (int j = 0; j < 4; j++) {
                unsigned long long wd = pack2(wj[j]);
                ffma2(acc[0][j], a01.x, wd);
                ffma2(acc[1][j], a01.y, wd);
                ffma2(acc[2][j], a23.x, wd);
                ffma2(acc[3][j], a23.y, wd);
            }
        }
        __syncthreads();
    }

    float4 bi = *(const float4*)(bih + colTile + c0);
    float4 bh = *(const float4*)(bhh + colTile + c0);
    float bias[4] = {bi.x + bh.x, bi.y + bh.y, bi.z + bh.z, bi.w + bh.w};
#pragma unroll
    for (int rp = 0; rp < 4; rp++) {
        float2 v0 = unpack2(acc[rp][0]);
        float2 v1 = unpack2(acc[rp][1]);
        float2 v2 = unpack2(acc[rp][2]);
        float2 v3 = unpack2(acc[rp][3]);
        size_t r = rowTile + r0 + rp * 2;
        *(float4*)(g_gx + r * 4096 + colTile + c0) =
            make_float4(v0.x + bias[0], v1.x + bias[1], v2.x + bias[2], v3.x + bias[3]);
        *(float4*)(g_gx + (r + 1) * 4096 + colTile + c0) =
            make_float4(v0.y + bias[0], v1.y + bias[1], v2.y + bias[2], v3.y + bias[3]);
    }
}

// ================= persistent recurrence (one layer, 512 steps) =================
// 128 blocks x 512 threads. Block owns hidden units [blk*8, blk*8+8), all 4 gates,
// all 32 batches. W_hh slice staged to SMEM once. h exchanged via UNIQUE per-step
// global buffers g_h[t][n][b] (write-once-then-read: no stale-cache hazard), with a
// gpu-scope release/acquire counting barrier between steps.
#define WROW 1028  // padded SMEM row stride (floats)
__global__ void __launch_bounds__(512, 1) lstm_persist(float* __restrict__ dout,
                                                       const float* __restrict__ Whh,
                                                       int layer, unsigned barBase) {
    extern __shared__ float sm[];
    float* sW = sm;                                    // [32][WROW]
    float4* red = (float4*)(sm + 32 * WROW);           // [16][256] float4
    float* hbuf = sm + 32 * WROW + 16 * 256 * 4;       // [256] floats

    const int tid = threadIdx.x;
    const int blk = blockIdx.x;

    // ---- stage W: sW row (g*8+u) = Whh[g*1024 + blk*8 + u][0..1024) ----
    for (int i = tid; i < 8192; i += 512) {            // 32 rows x 256 quads
        int row = i >> 8;
        int q   = i & 255;
        int srcRow = (row >> 3) * 1024 + blk * 8 + (row & 7);
        float4 v = *(const float4*)(Whh + (size_t)srcRow * 1024 + q * 4);
        *(float4*)(sW + (size_t)row * WROW + q * 4) = v;
    }
    __syncthreads();

    // matmul identity: 16 k-slices x 32 (unit, batch-group) threads
    const int ks = tid >> 5;           // 0..15, k in [ks*64, ks*64+64)
    const int u  = tid & 31;
    const int nl = u & 7;              // local unit 0..7
    const int b0 = (u >> 3) * 8;       // batch base: 0,8,16,24
    const int k0 = ks * 64;
    // pointwise identity (tid < 256): (batch pb, unit pn)
    const int pb = tid >> 3, pn = tid & 7;
    const int n2 = blk * 8 + pn;
    float c = 0.f;
    float* outbuf = (layer == 0) ? g_out0 : dout;

    for (int t = 0; t < 512; t++) {
        // gx prefetch for this (t, pb, n2)
        float gi = 0.f, gf = 0.f, gg_ = 0.f, go = 0.f;
        if (tid < 256) {
            const float* gxr = g_gx + ((size_t)t * 32 + pb) * 4096;
            gi  = gxr[n2];
            gf  = gxr[1024 + n2];
            gg_ = gxr[2048 + n2];
            go  = gxr[3072 + n2];
        }

        if (t > 0) {
            const float* hprev = g_h + (size_t)t * BH;  // written once, at step t-1
            unsigned long long acc[4][4];               // [gate][batch-pair]
#pragma unroll
            for (int g = 0; g < 4; g++)
#pragma unroll
                for (int p = 0; p < 4; p++) acc[g][p] = 0ull;

            for (int kk = 0; kk < 64; kk += 4) {
                int k = k0 + kk;
                float4 wv[4];
#pragma unroll
                for (int g = 0; g < 4; g++)
                    wv[g] = *(const float4*)(sW + (size_t)(g * 8 + nl) * WROW + k);
#pragma unroll
                for (int q = 0; q < 4; q++) {
                    const ulonglong2* hp = (const ulonglong2*)(hprev + (size_t)(k + q) * 32 + b0);
                    ulonglong2 hA = hp[0];    // batches b0..b0+3
                    ulonglong2 hB = hp[1];    // batches b0+4..b0+7
#pragma unroll
                    for (int g = 0; g < 4; g++) {
                        unsigned long long wd = pack2(((const float*)&wv[g])[q]);
                        ffma2(acc[g][0], hA.x, wd);
                        ffma2(acc[g][1], hA.y, wd);
                        ffma2(acc[g][2], hB.x, wd);
                        ffma2(acc[g][3], hB.y, wd);
                    }
                }
            }
            // partials -> red[ks][b*8 + nl] = {i,f,g,o}
#pragma unroll
            for (int p = 0; p < 4; p++) {
                float2 s0 = unpack2(acc[0][p]);
                float2 s1 = unpack2(acc[1][p]);
                float2 s2 = unpack2(acc[2][p]);
                float2 s3 = unpack2(acc[3][p]);
                red[ks * 256 + (b0 + p * 2 + 0) * 8 + nl] = make_float4(s0.x, s1.x, s2.x, s3.x);
                red[ks * 256 + (b0 + p * 2 + 1) * 8 + nl] = make_float4(s0.y, s1.y, s2.y, s3.y);
            }
        }
        __syncthreads();

        if (tid < 256) {
            if (t > 0) {
#pragma unroll
                for (int s = 0; s < 16; s++) {
                    float4 r = red[s * 256 + tid];     // tid == pb*8 + pn
                    gi += r.x; gf += r.y; gg_ += r.z; go += r.w;
                }
            }
            float c1 = sigm(gf) * c + sigm(gi) * tanhf(gg_);
            float h1 = sigm(go) * tanhf(c1);
            c = c1;
            outbuf[(size_t)t * BH + (size_t)pb * 1024 + n2] = h1;
            hbuf[pn * 32 + pb] = h1;                   // transposed [n_local][b]
        }
        __syncthreads();

        if (tid < 64) {  // publish transposed h block for step t into buffer t+1
            float4 v = *(const float4*)(hbuf + tid * 4);
            *(float4*)(g_h + (size_t)(t + 1) * BH + blk * 256 + tid * 4) = v;
        }
        __syncthreads();
        if (tid == 0) {  // gpu-scope release arrive + acquire spin
            bar_arrive_release();
            unsigned tgt = barBase + 128u * (unsigned)(t + 1);
            while (bar_peek_acquire() < tgt) { }
        }
        __syncthreads();
    }
    if (tid < 256) g_c[layer][pb * 1024 + n2] = c;
}

// ================= tail: (h_stack, c_stack) =================
__global__ void finalize(float* __restrict__ dout) {
    int idx = blockIdx.x * 256 + threadIdx.x;
    if (idx >= 4 * BH) return;
    int sec = idx >> 15, j = idx & 32767;
    float v;
    if (sec == 0)      v = g_out0[(size_t)511 * BH + j];  // h final, layer 0
    else if (sec == 1) v = dout[(size_t)511 * BH + j];    // h final, layer 1
    else               v = g_c[sec - 2][j];               // c final
    dout[OUTMAIN + idx] = v;
}

extern "C" void kernel_launch(void* const* d_in, const int* in_sizes, int n_in,
                              void* d_out, int out_size) {
    (void)in_sizes; (void)n_in; (void)out_size;
    const float* x    = (const float*)d_in[0];
    const float* Wih0 = (const float*)d_in[1];
    const float* Whh0 = (const float*)d_in[2];
    const float* bih0 = (const float*)d_in[3];
    const float* bhh0 = (const float*)d_in[4];
    const float* Wih1 = (const float*)d_in[5];
    const float* Whh1 = (const float*)d_in[6];
    const float* bih1 = (const float*)d_in[7];
    const float* bhh1 = (const float*)d_in[8];
    float* out = (float*)d_out;

    const int smemBytes = 32 * WROW * 4 + 16 * 256 * 16 + 1024;  // 198144
    cudaFuncSetAttribute(lstm_persist, cudaFuncAttributeMaxDynamicSharedMemorySize, smemBytes);

    dim3 ggrid(64, 128);
    zero_cnt<<<1, 1>>>();
    gx_gemm<<<ggrid, 256>>>(x, Wih0, bih0, bhh0, 1);
    lstm_persist<<<128, 512, smemBytes>>>(out, Whh0, 0, 0u);
    gx_gemm<<<ggrid, 256>>>(nullptr, Wih1, bih1, bhh1, 0);
    lstm_persist<<<128, 512, smemBytes>>>(out, Whh1, 1, 128u * 512u);
    finalize<<<512, 256>>>(out);
}